// round 3
// baseline (speedup 1.0000x reference)
#include <cuda_runtime.h>
#include <math_constants.h>

#define NDIM  512
#define NKNOT 32
#define NDATA 65536

#define DT   64            // dims per block tile (warp covers all 64: 2 dims/lane)
#define TPB  256           // 8 warps -> 8 rows per iteration
#define RPB  256           // rows per block

// Permuted layouts: within a 64-dim tile, dim d (dt = d & 63) maps to
// p = 32*(dt & 1) + (dt >> 1). Gather bank = 4*lane -> conflict-free for any k.
__device__ float4 g_K [NKNOT * NDIM];      // [k][tile*64 + p] = {xx,yy,dd,0}
__device__ float4 g_P2[4 * NDIM];          // [q][tile*64 + p] = {xx8q+1,8q+3,8q+5,0}
__device__ float  g_XE[(NKNOT / 2) * NDIM];// [j][tile*64 + p] = xx[2j]
__device__ float4 g_P1[NDIM];              // natural [d] = {xx7, xx15, xx23, inf}

// ---------------------------------------------------------------------------
__global__ void prep_kernel(const float* __restrict__ params) {
    int d = blockIdx.x * blockDim.x + threadIdx.x;
    if (d >= NDIM) return;

    const float* logdx    = params + 2 * NDIM + d * (NKNOT - 1);
    const float* logdy    = params + 2 * NDIM + NDIM * (NKNOT - 1) + d * (NKNOT - 1);
    const float* logderiv = params + 2 * NDIM + 2 * NDIM * (NKNOT - 1) + d * NKNOT;

    float xx[NKNOT], yy[NKNOT], dd[NKNOT];
    xx[0] = params[d];
    yy[0] = params[NDIM + d];
    dd[0] = expf(logderiv[0]);
    #pragma unroll
    for (int k = 1; k < NKNOT; k++) {
        xx[k] = xx[k - 1] + expf(logdx[k - 1]);
        yy[k] = yy[k - 1] + expf(logdy[k - 1]);
        dd[k] = expf(logderiv[k]);
    }

    const int dt = d & (DT - 1);
    const int dp = (d & ~(DT - 1)) + 32 * (dt & 1) + (dt >> 1);  // permuted index

    #pragma unroll
    for (int k = 0; k < NKNOT; k++)
        g_K[k * NDIM + dp] = make_float4(xx[k], yy[k], dd[k], 0.0f);
    #pragma unroll
    for (int q = 0; q < 4; q++)
        g_P2[q * NDIM + dp] = make_float4(xx[8 * q + 1], xx[8 * q + 3], xx[8 * q + 5], 0.0f);
    #pragma unroll
    for (int j = 0; j < NKNOT / 2; j++)
        g_XE[j * NDIM + dp] = xx[2 * j];

    g_P1[d] = make_float4(xx[7], xx[15], xx[23], CUDART_INF_F);
}

// ---------------------------------------------------------------------------
__device__ __forceinline__ void eval_one(
    const float xv, const int p,
    const float4* __restrict__ sK, const float4* __restrict__ sP2,
    const float* __restrict__ sXE, const float4 p1, const float xxlast,
    float& yv, float& ldv)
{
    // 4-ary tournament lower bound: base = min(#knots < xv, 31)
    const int q = (p1.x < xv) + (p1.y < xv) + (p1.z < xv);
    const float4 p2 = sP2[q * DT + p];
    const int t = (p2.x < xv) + (p2.y < xv) + (p2.z < xv);
    const int j = 4 * q + t;
    const int base = 2 * j + (sXE[j * DT + p] < xv);

    const bool sel0 = (base == 0);
    const bool selN = (xxlast < xv);

    const int ic = base > 1 ? base : 1;
    const float4 klo = sK[(ic - 1) * DT + p];
    const float4 khi = sK[ic * DT + p];

    const float x_lo = klo.x, y_lo = klo.y, dl = klo.z;
    const float x_hi = khi.x, y_hi = khi.y, dh = khi.z;

    // Mid branch; garbage for tail elements is fully overwritten below.
    const float inv_dx = __fdividef(1.0f, x_hi - x_lo);
    const float xi     = (xv - x_lo) * inv_dx;
    const float dy     = y_hi - y_lo;
    const float s      = dy * inv_dx;
    const float omxi   = 1.0f - xi;
    const float xi1    = xi * omxi;
    const float xi2    = xi * xi;
    const float den    = fmaf(dh + dl - 2.0f * s, xi1, s);
    const float inv_den = __fdividef(1.0f, den);
    float y  = fmaf(dy * fmaf(s, xi2, dl * xi1), inv_den, y_lo);
    const float num = fmaf(dh, xi2, fmaf(2.0f * s, xi1, dl * omxi * omxi));
    const float rs  = s * inv_den;
    float larg = rs * rs * num;          // 2log(s)+log(num)-2log(den)

    if (selN) { y = fmaf(xv - x_hi, dh, y_hi); larg = dh; }
    if (sel0) { y = fmaf(xv - x_lo, dl, y_lo); larg = dl; }
    yv  = y;
    ldv = __logf(larg);
}

__global__ __launch_bounds__(TPB, 4) void spline_kernel(
    const float* __restrict__ x, float* __restrict__ out)
{
    __shared__ float4 sK[NKNOT * DT];          // 32 KB
    __shared__ float4 sP2[4 * DT];             // 4 KB
    __shared__ float  sXE[(NKNOT / 2) * DT];   // 4 KB

    const int dbase = blockIdx.x * DT;
    const int tid = threadIdx.x;

    #pragma unroll
    for (int i = tid; i < NKNOT * DT; i += TPB)
        sK[i] = g_K[(i >> 6) * NDIM + dbase + (i & 63)];
    if (tid < 4 * DT)
        sP2[tid] = g_P2[(tid >> 6) * NDIM + dbase + (tid & 63)];
    #pragma unroll
    for (int i = tid; i < (NKNOT / 2) * DT; i += TPB)
        sXE[i] = g_XE[(i >> 6) * NDIM + dbase + (i & 63)];

    const int l  = tid & 31;
    const int w  = tid >> 5;                    // 0..7 (row lane)
    const int d0 = dbase + 2 * l;               // first of this thread's dim pair
    const int r0 = blockIdx.y * RPB;

    // Per-thread L1 pivots (read once, L2-cached).
    const float4 p1a = g_P1[d0];
    const float4 p1b = g_P1[d0 + 1];

    __syncthreads();

    const int pA = l;                           // perm index, i=0
    const int pB = 32 + l;                      // perm index, i=1
    const float xxlastA = sK[(NKNOT - 1) * DT + pA].x;
    const float xxlastB = sK[(NKNOT - 1) * DT + pB].x;

    float* __restrict__ yout  = out;
    float* __restrict__ ldout = out + (size_t)NDATA * NDIM;

    #pragma unroll 2
    for (int rr = w; rr < RPB; rr += TPB / 32) {
        const size_t off = (size_t)(r0 + rr) * NDIM + d0;
        const float2 xv2 = *reinterpret_cast<const float2*>(x + off);

        float ya, lda, yb, ldb;
        eval_one(xv2.x, pA, sK, sP2, sXE, p1a, xxlastA, ya, lda);
        eval_one(xv2.y, pB, sK, sP2, sXE, p1b, xxlastB, yb, ldb);

        *reinterpret_cast<float2*>(yout  + off) = make_float2(ya, yb);
        *reinterpret_cast<float2*>(ldout + off) = make_float2(lda, ldb);
    }
}

extern "C" void kernel_launch(void* const* d_in, const int* in_sizes, int n_in,
                              void* d_out, int out_size) {
    const float* x      = (const float*)d_in[0];
    const float* params = (const float*)d_in[1];
    float* out = (float*)d_out;

    prep_kernel<<<(NDIM + 255) / 256, 256>>>(params);

    dim3 grid(NDIM / DT, NDATA / RPB);
    spline_kernel<<<grid, TPB>>>(x, out);
}